// round 12
// baseline (speedup 1.0000x reference)
#include <cuda_runtime.h>
#include <cuda_fp16.h>
#include <mma.h>
#include <math.h>
#include <stdint.h>

using namespace nvcuda;

#define VV  50000
#define E   512
#define H   1024
#define B   256
#define S   256
#define G4H 4096
#define NCTA 128

// ---------------- static device scratch ----------------
__device__ __align__(256) __half g_emb16[(size_t)VV * E];
__device__ __align__(256) __half g_WhT[2][(size_t)G4H * H];   // [p=4h+g][k]  (n-major)
__device__ __align__(256) __half g_WxT[2][(size_t)G4H * E];   // [p][e]       (n-major)
__device__ float g_biasp[2][G4H];
__device__ float g_xproj[2][(size_t)S * B * G4H];             // [s*B+b][p], bias folded in
__device__ __align__(256) __half g_h16[2][2 * B * H];         // double-buffered h
__device__ unsigned g_bar_cnt;
__device__ volatile unsigned g_bar_rel;

__device__ __forceinline__ void cp16s(void* dst, const void* src) {
    unsigned d = (unsigned)__cvta_generic_to_shared(dst);
    asm volatile("cp.async.cg.shared.global [%0], [%1], 16;" :: "r"(d), "l"(src));
}
__device__ __forceinline__ void cpcommit() { asm volatile("cp.async.commit_group;"); }
template<int N> __device__ __forceinline__ void cpwait() { asm volatile("cp.async.wait_group %0;" :: "n"(N)); }

// ---------------- init ----------------
__global__ void zero_kernel() {
    int i = blockIdx.x * blockDim.x + threadIdx.x;
    if (i < 2 * 2 * B * H) ((__half*)g_h16)[i] = __float2half(0.f);
    if (i == 0) { g_bar_cnt = 0; g_bar_rel = 0; }
}

// ---------------- one-time prep: fp16 convert + permute/transpose ----------------
__global__ void prep_kernel(const float* __restrict__ Wh_f, const float* __restrict__ Wh_b,
                            const float* __restrict__ Wx_f, const float* __restrict__ Wx_b,
                            const float* __restrict__ b_f,  const float* __restrict__ b_b,
                            const float* __restrict__ emb) {
    const long T0 = (long)VV * E;
    const long T1 = 2L * G4H * H;
    const long T2 = 2L * G4H * E;
    const long T3 = 2L * G4H;
    const long total = T0 + T1 + T2 + T3;
    for (long id = (long)blockIdx.x * blockDim.x + threadIdx.x; id < total;
         id += (long)gridDim.x * blockDim.x) {
        if (id < T0) {
            g_emb16[id] = __float2half(emb[id]);
        } else if (id < T0 + T1) {
            long o = id - T0;
            int dir = o >= (long)G4H * H;
            long oo = o - (long)dir * G4H * H;
            int p = (int)(oo / H), k = (int)(oo % H);
            int h = p >> 2, g = p & 3;
            const float* src = dir ? Wh_b : Wh_f;
            g_WhT[dir][oo] = __float2half(src[(size_t)k * G4H + g * H + h]);
        } else if (id < T0 + T1 + T2) {
            long o = id - T0 - T1;
            int dir = o >= (long)G4H * E;
            long oo = o - (long)dir * G4H * E;
            int p = (int)(oo / E), k = (int)(oo % E);
            int h = p >> 2, g = p & 3;
            const float* src = dir ? Wx_b : Wx_f;
            g_WxT[dir][oo] = __float2half(src[(size_t)k * G4H + g * H + h]);
        } else {
            long o = id - T0 - T1 - T2;
            int dir = o >= G4H;
            int p = (int)(o - (long)dir * G4H);
            int h = p >> 2, g = p & 3;
            const float* src = dir ? b_b : b_f;
            g_biasp[dir][p] = src[g * H + h];
        }
    }
}

// ================= xproj (2-stage, unchanged from R10) =================
#define XAS_OFF(buf, r, c) ((buf) * 9216 + (r) * 72 + (c))
#define XBS_OFF(buf, r, c) (18432 + (buf) * 9216 + (r) * 72 + (c))
#define XPROJ_SMEM (36864 * 2)

__global__ void __launch_bounds__(512) xproj_kernel(const int* __restrict__ inputs) {
    extern __shared__ __align__(1024) __half sh[];
    __shared__ int toks[128];
    const int tid   = threadIdx.x;
    const int ntile = blockIdx.x;
    const int mtile = blockIdx.y;
    const int dir   = blockIdx.z;
    const int col0  = ntile * 128;
    const int row0  = mtile * 128;
    const __half* __restrict__ Bsrc = g_WxT[dir];

    if (tid < 128) {
        int row = row0 + tid;
        toks[tid] = inputs[(row & 255) * S + (row >> 8)];
    }
    __syncthreads();

    const int wid    = tid >> 5;
    const int warp_m = wid >> 2;
    const int warp_n = wid & 3;
    wmma::fragment<wmma::accumulator, 16, 16, 16, float> acc[2][2];
#pragma unroll
    for (int i = 0; i < 2; i++)
#pragma unroll
        for (int j = 0; j < 2; j++) wmma::fill_fragment(acc[i][j], 0.f);

    auto fill = [&](int buf, int k0) {
#pragma unroll
        for (int i = 0; i < 2; i++) {
            int u = tid + i * 512;
            int r = u >> 3, c8 = (u & 7) * 8;
            cp16s(&sh[XAS_OFF(buf, r, c8)], g_emb16 + (size_t)toks[r] * E + k0 + c8);
        }
#pragma unroll
        for (int i = 0; i < 2; i++) {
            int u = tid + i * 512;
            int r = u >> 3, c8 = (u & 7) * 8;
            cp16s(&sh[XBS_OFF(buf, r, c8)], Bsrc + (size_t)(col0 + r) * E + k0 + c8);
        }
    };
    fill(0, 0); cpcommit();
    const int NCHUNK = E / 64;
    for (int kc = 0; kc < NCHUNK; kc++) {
        int cur = kc & 1;
        if (kc + 1 < NCHUNK) { fill(cur ^ 1, (kc + 1) * 64); cpcommit(); cpwait<1>(); }
        else cpwait<0>();
        __syncthreads();
#pragma unroll
        for (int kf = 0; kf < 4; kf++) {
            wmma::fragment<wmma::matrix_a, 16, 16, 16, __half, wmma::row_major> af[2];
            wmma::fragment<wmma::matrix_b, 16, 16, 16, __half, wmma::col_major> bf[2];
#pragma unroll
            for (int i = 0; i < 2; i++)
                wmma::load_matrix_sync(af[i], &sh[XAS_OFF(cur, warp_m * 32 + i * 16, kf * 16)], 72);
#pragma unroll
            for (int j = 0; j < 2; j++)
                wmma::load_matrix_sync(bf[j], &sh[XBS_OFF(cur, warp_n * 32 + j * 16, kf * 16)], 72);
#pragma unroll
            for (int i = 0; i < 2; i++)
#pragma unroll
                for (int j = 0; j < 2; j++)
                    wmma::mma_sync(acc[i][j], af[i], bf[j], acc[i][j]);
        }
        __syncthreads();
    }
    float* sg = (float*)sh;
#pragma unroll
    for (int i = 0; i < 2; i++)
#pragma unroll
        for (int j = 0; j < 2; j++)
            wmma::store_matrix_sync(&sg[(warp_m * 32 + i * 16) * 132 + warp_n * 32 + j * 16],
                                    acc[i][j], 132, wmma::mem_row_major);
    __syncthreads();

    float* __restrict__ outp = g_xproj[dir] + (size_t)row0 * G4H + col0;
    const float* __restrict__ bp = g_biasp[dir] + col0;
    for (int q = tid; q < 128 * 32; q += 512) {
        int r = q >> 5, hl = q & 31;
        float4 v = *(const float4*)&sg[r * 132 + hl * 4];
        float4 bb = *(const float4*)(bp + hl * 4);
        v.x += bb.x; v.y += bb.y; v.z += bb.z; v.w += bb.w;
        *(float4*)(outp + (size_t)r * G4H + hl * 4) = v;
    }
}

// ================= persistent recurrent kernel =================
// smem layout identical to R10 step kernel:
//   3 stages x (A 128x72 | B 128x72) halfs           = 110592 B
//   xp_s: 128x128 floats @ float idx 27648           =  65536 B
//   c_s : 128x32  floats @ float idx 44032 (resident)=  16384 B
#define SAS_OFF(buf, r, c) ((buf) * 18432 + (r) * 72 + (c))
#define SBS_OFF(buf, r, c) ((buf) * 18432 + 9216 + (r) * 72 + (c))
#define XP_F 27648
#define C_F  44032
#define STEP_SMEM 192512

__device__ __forceinline__ void grid_barrier(unsigned gen) {
    __syncthreads();
    if (threadIdx.x == 0) {
        __threadfence();
        unsigned prev = atomicAdd(&g_bar_cnt, 1u);
        if (prev == (unsigned)NCTA * (gen + 1u) - 1u) {
            __threadfence();
            g_bar_rel = gen + 1u;
        } else {
            while (g_bar_rel < gen + 1u) { }
        }
        __threadfence();
    }
    __syncthreads();
}

__global__ void __launch_bounds__(512) lstm_persist_kernel() {
    extern __shared__ __align__(1024) __half sh[];
    float* shf = (float*)sh;
    const int tid   = threadIdx.x;
    const int bidx  = blockIdx.x;          // 0..127
    const int ntile = bidx & 31;
    const int mtile = bidx >> 5;           // 0..3
    const int col0  = ntile * 128;
    const int row0  = mtile * 128;         // global rows: dir*256+b
    const int dir   = mtile >> 1;
    const int b0    = row0 & 255;
    const __half* __restrict__ Bsrc = g_WhT[dir];

    const int wid    = tid >> 5;
    const int warp_m = wid >> 2;
    const int warp_n = wid & 3;

    // zero resident c slice
    for (int q = tid; q < 128 * 32; q += 512) shf[C_F + q] = 0.f;
    __syncthreads();

    const __half* Asrc = g_h16[0];

    auto fill = [&](int buf, int k0) {
#pragma unroll
        for (int i = 0; i < 2; i++) {
            int u = tid + i * 512;
            int r = u >> 3, c8 = (u & 7) * 8;
            cp16s(&sh[SAS_OFF(buf, r, c8)], Asrc + (size_t)(row0 + r) * H + k0 + c8);
        }
#pragma unroll
        for (int i = 0; i < 2; i++) {
            int u = tid + i * 512;
            int r = u >> 3, c8 = (u & 7) * 8;
            cp16s(&sh[SBS_OFF(buf, r, c8)], Bsrc + (size_t)(col0 + r) * H + k0 + c8);
        }
    };

    for (int t = 0; t < S; t++) {
        const int rbuf = t & 1;
        const int wbuf = rbuf ^ 1;
        Asrc = g_h16[rbuf];

        wmma::fragment<wmma::accumulator, 16, 16, 16, float> acc[2][2];
#pragma unroll
        for (int i = 0; i < 2; i++)
#pragma unroll
            for (int j = 0; j < 2; j++) wmma::fill_fragment(acc[i][j], 0.f);

        // F0, F1, then xp prefetch (own group)
        fill(0, 0);  cpcommit();
        fill(1, 64); cpcommit();
        const int sx = dir ? (S - 1 - t) : t;
        const float* __restrict__ xpb = g_xproj[dir] + ((size_t)sx * B + b0) * G4H + col0;
        {
#pragma unroll
            for (int i = 0; i < 8; i++) {           // 4096 float4s
                int u = tid + i * 512;
                int r = u >> 5, c4 = u & 31;
                cp16s(&shf[XP_F + r * 128 + c4 * 4], xpb + (size_t)r * G4H + c4 * 4);
            }
            cpcommit();
        }

        const int NCHUNK = H / 64;   // 16
        for (int kc = 0; kc < NCHUNK; kc++) {
            if (kc < 2) cpwait<2>();
            else if (kc + 1 < NCHUNK) cpwait<1>();
            else cpwait<0>();
            __syncthreads();
            if (kc + 2 < NCHUNK) { fill((kc + 2) % 3, (kc + 2) * 64); cpcommit(); }
            const int cur = kc % 3;
#pragma unroll
            for (int kf = 0; kf < 4; kf++) {
                wmma::fragment<wmma::matrix_a, 16, 16, 16, __half, wmma::row_major> af[2];
                wmma::fragment<wmma::matrix_b, 16, 16, 16, __half, wmma::col_major> bf[2];
#pragma unroll
                for (int i = 0; i < 2; i++)
                    wmma::load_matrix_sync(af[i], &sh[SAS_OFF(cur, warp_m * 32 + i * 16, kf * 16)], 72);
#pragma unroll
                for (int j = 0; j < 2; j++)
                    wmma::load_matrix_sync(bf[j], &sh[SBS_OFF(cur, warp_n * 32 + j * 16, kf * 16)], 72);
#pragma unroll
                for (int i = 0; i < 2; i++)
#pragma unroll
                    for (int j = 0; j < 2; j++)
                        wmma::mma_sync(acc[i][j], af[i], bf[j], acc[i][j]);
            }
        }
        __syncthreads();

        // stage gates into stage region as float [128][132]
        float* sg = shf;
#pragma unroll
        for (int i = 0; i < 2; i++)
#pragma unroll
            for (int j = 0; j < 2; j++)
                wmma::store_matrix_sync(&sg[(warp_m * 32 + i * 16) * 132 + warp_n * 32 + j * 16],
                                        acc[i][j], 132, wmma::mem_row_major);
        __syncthreads();

        // fused LSTM cell: gates + xp from smem, c resident in smem, h -> global (write buffer)
        __half* __restrict__ hout = g_h16[wbuf];
        for (int q = tid; q < 128 * 32; q += 512) {
            int r  = q >> 5;
            int hl = q & 31;
            int grow = row0 + r;
            float4 gv = *(const float4*)&sg[r * 132 + hl * 4];
            float4 xv = *(const float4*)&shf[XP_F + r * 128 + hl * 4];
            float cprev = shf[C_F + r * 32 + hl];
            float i_ = 1.f / (1.f + expf(-(gv.x + xv.x)));
            float f_ = 1.f / (1.f + expf(-(gv.y + xv.y)));
            float o_ = 1.f / (1.f + expf(-(gv.z + xv.z)));
            float ct = tanhf(gv.w + xv.w);
            float c = f_ * cprev + i_ * ct;
            shf[C_F + r * 32 + hl] = c;
            hout[(size_t)grow * H + (col0 >> 2) + hl] = __float2half(o_ * tanhf(c));
        }

        grid_barrier((unsigned)t);
    }
}

// ---------------- head: (h_f + h_b) @ W_hq + b_q, softmax ----------------
__global__ void final_kernel(const float* __restrict__ W_hq,
                             const float* __restrict__ b_q,
                             float* __restrict__ out) {
    __shared__ float sm[256][10];
    int b   = blockIdx.x;
    int tid = threadIdx.x;

    float acc[10];
#pragma unroll
    for (int q = 0; q < 10; q++) acc[q] = 0.f;

    const __half* __restrict__ hfin = g_h16[0];   // t=255 writes buffer 0
    for (int h = tid; h < H; h += 256) {
        float hv = __half2float(hfin[b * H + h]) + __half2float(hfin[(B + b) * H + h]);
#pragma unroll
        for (int q = 0; q < 10; q++) acc[q] += hv * W_hq[h * 10 + q];
    }
#pragma unroll
    for (int q = 0; q < 10; q++) sm[tid][q] = acc[q];
    __syncthreads();

    for (int off = 128; off > 0; off >>= 1) {
        if (tid < off) {
#pragma unroll
            for (int q = 0; q < 10; q++) sm[tid][q] += sm[tid + off][q];
        }
        __syncthreads();
    }

    if (tid == 0) {
        float lg[10], mx = -1e30f;
#pragma unroll
        for (int q = 0; q < 10; q++) { lg[q] = sm[0][q] + b_q[q]; mx = fmaxf(mx, lg[q]); }
        float sum = 0.f;
#pragma unroll
        for (int q = 0; q < 10; q++) { lg[q] = expf(lg[q] - mx); sum += lg[q]; }
        float inv = 1.f / sum;
#pragma unroll
        for (int q = 0; q < 10; q++) out[b * 10 + q] = lg[q] * inv;
    }
}

// ---------------- launch ----------------
extern "C" void kernel_launch(void* const* d_in, const int* in_sizes, int n_in,
                              void* d_out, int out_size) {
    const int*   inputs = (const int*)  d_in[0];
    const float* emb    = (const float*)d_in[1];
    const float* Wx_f   = (const float*)d_in[2];
    const float* Wh_f   = (const float*)d_in[3];
    const float* b_f    = (const float*)d_in[4];
    const float* Wx_b   = (const float*)d_in[5];
    const float* Wh_b   = (const float*)d_in[6];
    const float* b_b    = (const float*)d_in[7];
    const float* W_hq   = (const float*)d_in[8];
    const float* b_q    = (const float*)d_in[9];
    float* out = (float*)d_out;

    cudaFuncSetAttribute(xproj_kernel, cudaFuncAttributeMaxDynamicSharedMemorySize, XPROJ_SMEM);
    cudaFuncSetAttribute(lstm_persist_kernel, cudaFuncAttributeMaxDynamicSharedMemorySize, STEP_SMEM);

    zero_kernel<<<4096, 256>>>();
    prep_kernel<<<8192, 256>>>(Wh_f, Wh_b, Wx_f, Wx_b, b_f, b_b, emb);

    xproj_kernel<<<dim3(32, 512, 2), 512, XPROJ_SMEM>>>(inputs);

    lstm_persist_kernel<<<NCTA, 512, STEP_SMEM>>>();

    final_kernel<<<256, 256>>>(W_hq, b_q, out);
}